// round 2
// baseline (speedup 1.0000x reference)
#include <cuda_runtime.h>
#include <cuda_bf16.h>
#include <math.h>
#include <float.h>

// ---------------------------------------------------------------------------
// Problem constants
// ---------------------------------------------------------------------------
#define B        4
#define N        2048
#define DIM      512
#define HEADS    8
#define DHEAD    64
#define INNER    512           // HEADS*DHEAD
#define ROWS     (B*N)         // 8192
#define NARROW_K 9
#define WIDE_K   9
#define WIDE_DIL 5

// ---------------------------------------------------------------------------
// Device scratch (static allocation; no cudaMalloc allowed)
// ---------------------------------------------------------------------------
__device__ float g_qkv[ROWS * 3 * INNER];     // 8192 x 1536
__device__ float g_qs [ROWS * INNER];         // softmaxed q * 0.125
__device__ float g_ks [ROWS * INNER];         // column-softmaxed k
__device__ float g_vm [ROWS * INNER];         // masked v
__device__ float g_ctx_part[B*HEADS*8*DHEAD*DHEAD];
__device__ float g_ctx[B*HEADS*DHEAD*DHEAD];
__device__ float g_attn[ROWS * INNER];        // attn before out-proj
__device__ float g_tok [ROWS * DIM];          // after out-proj (+bias)
__device__ float g_xm  [ROWS * DIM];          // masked conv input
__device__ float g_wkn [NARROW_K*DIM*DIM];    // [k][ci][co]
__device__ float g_wkw [WIDE_K*DIM*DIM];
__device__ float g_c1  [ROWS * DIM];          // tok + gelu(narrow)
__device__ float g_c2  [ROWS * DIM];          // c1 + gelu(wide)
__device__ float g_ln1 [ROWS * DIM];
__device__ float g_ff  [ROWS * DIM];
__device__ int   g_mask[ROWS];

// ---------------------------------------------------------------------------
// Helpers
// ---------------------------------------------------------------------------
__device__ __forceinline__ float gelu_exact(float x) {
    return 0.5f * x * (1.0f + erff(x * 0.7071067811865476f));
}

// ---------------------------------------------------------------------------
// Mask normalization: detect bool-byte vs int32 storage, write int mask
// ---------------------------------------------------------------------------
__global__ void mask_prep_kernel(const unsigned char* raw) {
    __shared__ int is_bool;
    if (threadIdx.x == 0) is_bool = 0;
    __syncthreads();
    // If storage is int32 with values {0,1}, every byte at p%4!=0 is 0.
    // If storage is bool bytes (random 0/1 over 8192), some will be nonzero.
    for (int p = threadIdx.x; p < ROWS; p += blockDim.x) {
        if ((p & 3) && raw[p]) is_bool = 1;
    }
    __syncthreads();
    const int* as_int = (const int*)raw;
    for (int i = threadIdx.x; i < ROWS; i += blockDim.x) {
        g_mask[i] = is_bool ? (raw[i] != 0) : (as_int[i] != 0);
    }
}

// ---------------------------------------------------------------------------
// Generic tiled SGEMM: C[M,N] = A[M,K] * B[K,N] (+bias) (optional gelu)
// 64x64 block tile, 256 threads, 4x4 per thread, K step 16
// ---------------------------------------------------------------------------
__global__ void sgemm64_kernel(const float* __restrict__ A,
                               const float* __restrict__ Bm,
                               const float* __restrict__ bias,
                               float* __restrict__ C,
                               int M, int Nn, int K, int do_gelu) {
    __shared__ float As[16][64];
    __shared__ float Bs[16][64];
    const int n0 = blockIdx.x * 64;
    const int m0 = blockIdx.y * 64;
    const int tid = threadIdx.x;
    const int ty = tid >> 4, tx = tid & 15;

    float acc[4][4];
#pragma unroll
    for (int i = 0; i < 4; i++)
#pragma unroll
        for (int j = 0; j < 4; j++) acc[i][j] = 0.f;

    for (int k0 = 0; k0 < K; k0 += 16) {
        // load A tile: As[k][m]
#pragma unroll
        for (int i = 0; i < 4; i++) {
            int e = tid + 256 * i;           // 0..1023
            int kk = e & 15, m = e >> 4;
            As[kk][m] = A[(size_t)(m0 + m) * K + k0 + kk];
        }
        // load B tile: Bs[k][n]
#pragma unroll
        for (int i = 0; i < 4; i++) {
            int e = tid + 256 * i;
            int nn = e & 63, kk = e >> 6;
            Bs[kk][nn] = Bm[(size_t)(k0 + kk) * Nn + n0 + nn];
        }
        __syncthreads();
#pragma unroll
        for (int kk = 0; kk < 16; kk++) {
            float a[4], b[4];
#pragma unroll
            for (int i = 0; i < 4; i++) a[i] = As[kk][ty * 4 + i];
#pragma unroll
            for (int j = 0; j < 4; j++) b[j] = Bs[kk][tx * 4 + j];
#pragma unroll
            for (int i = 0; i < 4; i++)
#pragma unroll
                for (int j = 0; j < 4; j++) acc[i][j] = fmaf(a[i], b[j], acc[i][j]);
        }
        __syncthreads();
    }
#pragma unroll
    for (int i = 0; i < 4; i++) {
        int row = m0 + ty * 4 + i;
#pragma unroll
        for (int j = 0; j < 4; j++) {
            int col = n0 + tx * 4 + j;
            float v = acc[i][j];
            if (bias) v += bias[col];
            if (do_gelu) v = gelu_exact(v);
            C[(size_t)row * Nn + col] = v;
        }
    }
}

// ---------------------------------------------------------------------------
// q softmax (+rope, *0.125) and masked v. One block per token row.
// ---------------------------------------------------------------------------
__global__ void q_v_kernel() {
    const int row = blockIdx.x;            // 0..8191
    const int pos = row & (N - 1);
    const int tid = threadIdx.x;           // 256
    const int w = tid >> 5;                // head
    const int l = tid & 31;

    // q part: lane l handles d=l and d=l+32 of head w
    float inv = expf(-(float)(2 * l) * (1.0f / 64.0f) * logf(10000.0f));
    float arg = (float)pos * inv;
    const float* qrow = g_qkv + (size_t)row * (3 * INNER);
    float x1 = qrow[w * 64 + l]      + sinf(arg);
    float x2 = qrow[w * 64 + l + 32] + cosf(arg);
    float m = fmaxf(x1, x2);
#pragma unroll
    for (int o = 16; o > 0; o >>= 1) m = fmaxf(m, __shfl_xor_sync(0xffffffffu, m, o));
    float e1 = expf(x1 - m), e2 = expf(x2 - m);
    float s = e1 + e2;
#pragma unroll
    for (int o = 16; o > 0; o >>= 1) s += __shfl_xor_sync(0xffffffffu, s, o);
    float r = 0.125f / s;
    g_qs[(size_t)row * INNER + w * 64 + l]      = e1 * r;
    g_qs[(size_t)row * INNER + w * 64 + l + 32] = e2 * r;

    // v part: masked
    float mk = g_mask[row] ? 1.0f : 0.0f;
    for (int i = tid; i < INNER; i += 256)
        g_vm[(size_t)row * INNER + i] = mk * qrow[2 * INNER + i];
}

// ---------------------------------------------------------------------------
// k column softmax over the sequence axis. One block per (b, col=h*64+d).
// Each thread caches its 8 column entries in registers.
// ---------------------------------------------------------------------------
__global__ void k_colsoftmax_kernel() {
    const int col = blockIdx.x;            // 0..511
    const int b = blockIdx.y;
    const int d = col & 63;
    const int tid = threadIdx.x;           // 256
    __shared__ float red[256];

    int i_ = (d < 32) ? d : (d - 32);
    float inv = expf(-(float)(2 * i_) * (1.0f / 64.0f) * logf(10000.0f));
    bool use_sin = (d < 32);

    float vals[8];
    float mx = -FLT_MAX;
#pragma unroll
    for (int j = 0; j < 8; j++) {
        int n = tid + 256 * j;
        int row = b * N + n;
        float arg = (float)n * inv;
        float rope = use_sin ? sinf(arg) : cosf(arg);
        float v = g_qkv[(size_t)row * (3 * INNER) + INNER + col] + rope;
        v = g_mask[row] ? v : -FLT_MAX;
        vals[j] = v;
        mx = fmaxf(mx, v);
    }
    red[tid] = mx; __syncthreads();
    for (int o = 128; o > 0; o >>= 1) {
        if (tid < o) red[tid] = fmaxf(red[tid], red[tid + o]);
        __syncthreads();
    }
    mx = red[0]; __syncthreads();

    float s = 0.f;
    float ev[8];
#pragma unroll
    for (int j = 0; j < 8; j++) {
        ev[j] = (vals[j] == -FLT_MAX) ? 0.f : expf(vals[j] - mx);
        s += ev[j];
    }
    red[tid] = s; __syncthreads();
    for (int o = 128; o > 0; o >>= 1) {
        if (tid < o) red[tid] += red[tid + o];
        __syncthreads();
    }
    float rs = 1.0f / red[0];
#pragma unroll
    for (int j = 0; j < 8; j++) {
        int n = tid + 256 * j;
        g_ks[(size_t)(b * N + n) * INNER + col] = ev[j] * rs;
    }
}

// ---------------------------------------------------------------------------
// context partial: ctx[b,h,d,e] = sum_n ks[b,n,hd]*vm[b,n,he]; n split by 8
// ---------------------------------------------------------------------------
__global__ void ctx_partial_kernel() {
    const int bh = blockIdx.x;             // 0..31
    const int split = blockIdx.y;          // 0..7
    const int b = bh >> 3, h = bh & 7;
    const int tid = threadIdx.x;           // 256
    const int ty = tid >> 4, tx = tid & 15;
    __shared__ float Ks[16][64];
    __shared__ float Vs[16][64];

    float acc[4][4];
#pragma unroll
    for (int i = 0; i < 4; i++)
#pragma unroll
        for (int j = 0; j < 4; j++) acc[i][j] = 0.f;

    const int n0 = split * 256;
    for (int c = 0; c < 16; c++) {
        int nb = n0 + c * 16;
        int r = tid >> 6, colc = tid & 63;
#pragma unroll
        for (int i = 0; i < 4; i++) {
            int rr = r + 4 * i;
            size_t base = (size_t)(b * N + nb + rr) * INNER + h * 64 + colc;
            Ks[rr][colc] = g_ks[base];
            Vs[rr][colc] = g_vm[base];
        }
        __syncthreads();
#pragma unroll
        for (int kk = 0; kk < 16; kk++) {
            float a[4], bb[4];
#pragma unroll
            for (int i = 0; i < 4; i++) a[i] = Ks[kk][ty * 4 + i];
#pragma unroll
            for (int j = 0; j < 4; j++) bb[j] = Vs[kk][tx * 4 + j];
#pragma unroll
            for (int i = 0; i < 4; i++)
#pragma unroll
                for (int j = 0; j < 4; j++) acc[i][j] = fmaf(a[i], bb[j], acc[i][j]);
        }
        __syncthreads();
    }
    float* dst = g_ctx_part + (size_t)(bh * 8 + split) * 4096;
#pragma unroll
    for (int i = 0; i < 4; i++)
#pragma unroll
        for (int j = 0; j < 4; j++)
            dst[(ty * 4 + i) * 64 + tx * 4 + j] = acc[i][j];
}

__global__ void ctx_reduce_kernel() {
    int i = blockIdx.x * blockDim.x + threadIdx.x;
    if (i >= B * HEADS * 4096) return;
    int bh = i >> 12, pos = i & 4095;
    float s = 0.f;
#pragma unroll
    for (int sp = 0; sp < 8; sp++) s += g_ctx_part[(size_t)(bh * 8 + sp) * 4096 + pos];
    g_ctx[i] = s;
}

// ---------------------------------------------------------------------------
// attn out: out[b,n,h*64+e] = sum_d ctx[b,h,d,e] * qs[b,n,h*64+d]
// one block handles (b,h, 32 tokens)
// ---------------------------------------------------------------------------
__global__ void attn_apply_kernel() {
    const int blk = blockIdx.x;            // 4*8*64 = 2048
    const int tile = blk & 63;
    const int h = (blk >> 6) & 7;
    const int b = blk >> 9;
    const int t0 = tile * 32;
    const int tid = threadIdx.x;           // 256
    __shared__ float ctx_sh[64 * 65];
    __shared__ float qs_sh[32 * 64];

    const float* ctxp = g_ctx + (size_t)(b * 8 + h) * 4096;
#pragma unroll
    for (int i = 0; i < 16; i++) {
        int idx = tid + 256 * i;
        ctx_sh[(idx >> 6) * 65 + (idx & 63)] = ctxp[idx];
    }
#pragma unroll
    for (int i = 0; i < 8; i++) {
        int idx = tid + 256 * i;            // 0..2047
        int tok = idx >> 6, d = idx & 63;
        qs_sh[idx] = g_qs[(size_t)(b * N + t0 + tok) * INNER + h * 64 + d];
    }
    __syncthreads();
#pragma unroll
    for (int o = 0; o < 8; o++) {
        int idx = tid + 256 * o;
        int tok = idx >> 6, e = idx & 63;
        float s = 0.f;
#pragma unroll
        for (int d = 0; d < 64; d++)
            s = fmaf(qs_sh[tok * 64 + d], ctx_sh[d * 65 + e], s);
        g_attn[(size_t)(b * N + t0 + tok) * INNER + h * 64 + e] = s;
    }
}

// ---------------------------------------------------------------------------
// masked conv input
// ---------------------------------------------------------------------------
__global__ void mask_apply_kernel() {
    size_t i = (size_t)blockIdx.x * blockDim.x + threadIdx.x;
    if (i >= (size_t)ROWS * DIM) return;
    g_xm[i] = g_mask[i >> 9] ? g_tok[i] : 0.f;
}

// ---------------------------------------------------------------------------
// weight transpose: w[co][ci][k] -> wk[k][ci][co]
// ---------------------------------------------------------------------------
__global__ void wtrans_kernel(const float* __restrict__ w, float* __restrict__ wk, int Kt) {
    int idx = blockIdx.x * blockDim.x + threadIdx.x;
    int total = DIM * DIM * Kt;
    if (idx >= total) return;
    int co = idx / (DIM * Kt);
    int r = idx - co * (DIM * Kt);
    int ci = r / Kt;
    int k = r - ci * Kt;
    wk[((size_t)k * DIM + ci) * DIM + co] = w[idx];
}

// ---------------------------------------------------------------------------
// implicit-GEMM dilated conv1d: out[b,t,co] = base + gelu(bias + sum_{k,ci} ...)
// grid: (co_tiles=8, t_tiles=32, b=4), block 256
// ---------------------------------------------------------------------------
__global__ void conv_gemm_kernel(const float* __restrict__ wk,
                                 const float* __restrict__ bias,
                                 const float* __restrict__ base,
                                 float* __restrict__ out, int dil) {
    __shared__ float Xs[16][65];
    __shared__ float Ws[16][64];
    const int co0 = blockIdx.x * 64;
    const int t0 = blockIdx.y * 64;
    const int b = blockIdx.z;
    const int tid = threadIdx.x;
    const int ty = tid >> 4, tx = tid & 15;

    float acc[4][4];
#pragma unroll
    for (int i = 0; i < 4; i++)
#pragma unroll
        for (int j = 0; j < 4; j++) acc[i][j] = 0.f;

    for (int k = 0; k < 9; k++) {
        const int shift = (k - 4) * dil;
        for (int ci0 = 0; ci0 < DIM; ci0 += 16) {
            // X tile: Xs[kk][t]
#pragma unroll
            for (int i = 0; i < 4; i++) {
                int e = tid + 256 * i;          // 0..1023
                int kk = e & 15, t = e >> 4;
                int tt = t0 + t + shift;
                float v = 0.f;
                if (tt >= 0 && tt < N)
                    v = g_xm[(size_t)(b * N + tt) * DIM + ci0 + kk];
                Xs[kk][t] = v;
            }
            // W tile: Ws[kk][co]
#pragma unroll
            for (int i = 0; i < 4; i++) {
                int e = tid + 256 * i;
                int co = e & 63, kk = e >> 6;
                Ws[kk][co] = wk[((size_t)k * DIM + ci0 + kk) * DIM + co0 + co];
            }
            __syncthreads();
#pragma unroll
            for (int kk = 0; kk < 16; kk++) {
                float a[4], bb[4];
#pragma unroll
                for (int i = 0; i < 4; i++) a[i] = Xs[kk][ty * 4 + i];
#pragma unroll
                for (int j = 0; j < 4; j++) bb[j] = Ws[kk][tx * 4 + j];
#pragma unroll
                for (int i = 0; i < 4; i++)
#pragma unroll
                    for (int j = 0; j < 4; j++) acc[i][j] = fmaf(a[i], bb[j], acc[i][j]);
            }
            __syncthreads();
        }
    }
#pragma unroll
    for (int i = 0; i < 4; i++) {
        int t = t0 + ty * 4 + i;
#pragma unroll
        for (int j = 0; j < 4; j++) {
            int co = co0 + tx * 4 + j;
            size_t idx = (size_t)(b * N + t) * DIM + co;
            out[idx] = base[idx] + gelu_exact(acc[i][j] + bias[co]);
        }
    }
}

// ---------------------------------------------------------------------------
// layer norm over last dim (512). One block per row.
// ---------------------------------------------------------------------------
__global__ void ln_kernel(const float* __restrict__ x,
                          const float* __restrict__ g,
                          const float* __restrict__ bvec,
                          float* __restrict__ out) {
    const int row = blockIdx.x;
    const int tid = threadIdx.x;   // 256
    __shared__ float red[256];
    float v0 = x[(size_t)row * DIM + tid];
    float v1 = x[(size_t)row * DIM + tid + 256];
    red[tid] = v0 + v1; __syncthreads();
    for (int o = 128; o > 0; o >>= 1) {
        if (tid < o) red[tid] += red[tid + o];
        __syncthreads();
    }
    float mean = red[0] * (1.0f / DIM); __syncthreads();
    float d0 = v0 - mean, d1 = v1 - mean;
    red[tid] = d0 * d0 + d1 * d1; __syncthreads();
    for (int o = 128; o > 0; o >>= 1) {
        if (tid < o) red[tid] += red[tid + o];
        __syncthreads();
    }
    float var = red[0] * (1.0f / DIM);
    float rstd = rsqrtf(var + 1e-5f);
    out[(size_t)row * DIM + tid]       = d0 * rstd * g[tid] + bvec[tid];
    out[(size_t)row * DIM + tid + 256] = d1 * rstd * g[tid + 256] + bvec[tid + 256];
}

// ---------------------------------------------------------------------------
// Launch
// ---------------------------------------------------------------------------
extern "C" void kernel_launch(void* const* d_in, const int* in_sizes, int n_in,
                              void* d_out, int out_size) {
    const float* tokens   = (const float*)d_in[0];
    const unsigned char* mask_raw = (const unsigned char*)d_in[1];
    const float* w_qkv    = (const float*)d_in[2];
    const float* w_out    = (const float*)d_in[3];
    const float* b_out    = (const float*)d_in[4];
    const float* w_narrow = (const float*)d_in[5];
    const float* b_narrow = (const float*)d_in[6];
    const float* w_wide   = (const float*)d_in[7];
    const float* b_wide   = (const float*)d_in[8];
    const float* ln1_g    = (const float*)d_in[9];
    const float* ln1_b    = (const float*)d_in[10];
    const float* ff_w     = (const float*)d_in[11];
    const float* ff_b     = (const float*)d_in[12];
    const float* ln2_g    = (const float*)d_in[13];
    const float* ln2_b    = (const float*)d_in[14];
    float* outp = (float*)d_out;

    float *p_qkv, *p_qs, *p_ks, *p_vm, *p_attn, *p_tok, *p_xm;
    float *p_wkn, *p_wkw, *p_c1, *p_c2, *p_ln1, *p_ff;
    cudaGetSymbolAddress((void**)&p_qkv, g_qkv);
    cudaGetSymbolAddress((void**)&p_qs,  g_qs);
    cudaGetSymbolAddress((void**)&p_ks,  g_ks);
    cudaGetSymbolAddress((void**)&p_vm,  g_vm);
    cudaGetSymbolAddress((void**)&p_attn,g_attn);
    cudaGetSymbolAddress((void**)&p_tok, g_tok);
    cudaGetSymbolAddress((void**)&p_xm,  g_xm);
    cudaGetSymbolAddress((void**)&p_wkn, g_wkn);
    cudaGetSymbolAddress((void**)&p_wkw, g_wkw);
    cudaGetSymbolAddress((void**)&p_c1,  g_c1);
    cudaGetSymbolAddress((void**)&p_c2,  g_c2);
    cudaGetSymbolAddress((void**)&p_ln1, g_ln1);
    cudaGetSymbolAddress((void**)&p_ff,  g_ff);

    // 1. mask
    mask_prep_kernel<<<1, 256>>>(mask_raw);

    // 2. qkv GEMM: (8192 x 512) @ (512 x 1536)
    sgemm64_kernel<<<dim3(3 * INNER / 64, ROWS / 64), 256>>>(
        tokens, w_qkv, nullptr, p_qkv, ROWS, 3 * INNER, DIM, 0);

    // 3. q softmax + masked v
    q_v_kernel<<<ROWS, 256>>>();

    // 4. k column softmax
    k_colsoftmax_kernel<<<dim3(INNER, B), 256>>>();

    // 5. context
    ctx_partial_kernel<<<dim3(B * HEADS, 8), 256>>>();
    ctx_reduce_kernel<<<(B * HEADS * 4096 + 255) / 256, 256>>>();

    // 6. apply context to q
    attn_apply_kernel<<<B * HEADS * (N / 32), 256>>>();

    // 7. out projection (+bias)
    sgemm64_kernel<<<dim3(DIM / 64, ROWS / 64), 256>>>(
        p_attn, w_out, b_out, p_tok, ROWS, DIM, INNER, 0);

    // 8. masked conv input
    mask_apply_kernel<<<(ROWS * DIM + 255) / 256, 256>>>();

    // 9. conv weight transposes
    wtrans_kernel<<<(DIM * DIM * NARROW_K + 255) / 256, 256>>>(w_narrow, p_wkn, NARROW_K);
    wtrans_kernel<<<(DIM * DIM * WIDE_K + 255) / 256, 256>>>(w_wide, p_wkw, WIDE_K);

    // 10. convs (implicit GEMM) with fused residual + gelu
    conv_gemm_kernel<<<dim3(DIM / 64, N / 64, B), 256>>>(p_wkn, b_narrow, p_tok, p_c1, 1);
    conv_gemm_kernel<<<dim3(DIM / 64, N / 64, B), 256>>>(p_wkw, b_wide, p_c1, p_c2, WIDE_DIL);

    // 11. ln1
    ln_kernel<<<ROWS, 256>>>(p_c2, ln1_g, ln1_b, p_ln1);

    // 12. ff GEMM + bias + gelu
    sgemm64_kernel<<<dim3(DIM / 64, ROWS / 64), 256>>>(
        p_ln1, ff_w, ff_b, p_ff, ROWS, DIM, DIM, 1);

    // 13. ln2 -> output
    ln_kernel<<<ROWS, 256>>>(p_ff, ln2_g, ln2_b, outp);
}

// round 3
// speedup vs baseline: 1.0678x; 1.0678x over previous
#include <cuda_runtime.h>
#include <cuda_bf16.h>
#include <math.h>
#include <float.h>

// ---------------------------------------------------------------------------
// Problem constants
// ---------------------------------------------------------------------------
#define B        4
#define N        2048
#define DIM      512
#define HEADS    8
#define DHEAD    64
#define INNER    512
#define ROWS     (B*N)
#define NARROW_K 9
#define WIDE_K   9
#define WIDE_DIL 5

// ---------------------------------------------------------------------------
// Device scratch
// ---------------------------------------------------------------------------
__device__ float g_qkv[ROWS * 3 * INNER];
__device__ float g_qs [ROWS * INNER];
__device__ float g_ks [ROWS * INNER];
__device__ float g_vm [ROWS * INNER];
__device__ float g_ctx_part[B*HEADS*8*DHEAD*DHEAD];
__device__ float g_ctx[B*HEADS*DHEAD*DHEAD];
__device__ float g_attn[ROWS * INNER];
__device__ float g_tok [ROWS * DIM];
__device__ float g_xm  [ROWS * DIM];
__device__ float g_wkn [NARROW_K*DIM*DIM];
__device__ float g_wkw [WIDE_K*DIM*DIM];
__device__ float g_c1  [ROWS * DIM];
__device__ float g_c2  [ROWS * DIM];
__device__ float g_ln1 [ROWS * DIM];
__device__ float g_ff  [ROWS * DIM];
__device__ int   g_mask[ROWS];

// ---------------------------------------------------------------------------
// Helpers
// ---------------------------------------------------------------------------
__device__ __forceinline__ float gelu_exact(float x) {
    return 0.5f * x * (1.0f + erff(x * 0.7071067811865476f));
}
__device__ __forceinline__ unsigned long long pack2(float x, float y) {
    unsigned long long r;
    asm("mov.b64 %0, {%1, %2};" : "=l"(r) : "f"(x), "f"(y));
    return r;
}
__device__ __forceinline__ void fma2(unsigned long long &d,
                                     unsigned long long a,
                                     unsigned long long b) {
    asm("fma.rn.f32x2 %0, %1, %2, %0;" : "+l"(d) : "l"(a), "l"(b));
}
__device__ __forceinline__ float2 unpack2(unsigned long long v) {
    float2 r;
    asm("mov.b64 {%0, %1}, %2;" : "=f"(r.x), "=f"(r.y) : "l"(v));
    return r;
}

// ---------------------------------------------------------------------------
// Mask normalization: detect bool-byte vs int32 storage
// ---------------------------------------------------------------------------
__global__ void mask_prep_kernel(const unsigned char* raw) {
    __shared__ int is_bool;
    if (threadIdx.x == 0) is_bool = 0;
    __syncthreads();
    for (int p = threadIdx.x; p < ROWS; p += blockDim.x) {
        if ((p & 3) && raw[p]) is_bool = 1;
    }
    __syncthreads();
    const int* as_int = (const int*)raw;
    for (int i = threadIdx.x; i < ROWS; i += blockDim.x) {
        g_mask[i] = is_bool ? (raw[i] != 0) : (as_int[i] != 0);
    }
}

// ---------------------------------------------------------------------------
// 128x128 SGEMM, 256 threads, 8x8/thread via packed f32x2 FMA, K step 8,
// register-prefetch pipelining. Optional bias / gelu / masked secondary store.
// ---------------------------------------------------------------------------
__global__ void sgemm128_kernel(const float* __restrict__ A,
                                const float* __restrict__ Bm,
                                const float* __restrict__ bias,
                                float* __restrict__ C,
                                float* __restrict__ C2masked,
                                int M, int Nn, int K, int do_gelu) {
    __shared__ float As[8][132];
    __shared__ float Bs[8][128];
    const int n0 = blockIdx.x * 128;
    const int m0 = blockIdx.y * 128;
    const int tid = threadIdx.x;
    const int tx = tid & 15, ty = tid >> 4;

    const int arow = tid >> 1;          // 0..127
    const int akq  = (tid & 1) * 4;     // 0 or 4
    const int bkk  = tid >> 5;          // 0..7
    const int bnq  = (tid & 31) * 4;    // 0..124

    const float* Aptr = A + (size_t)(m0 + arow) * K + akq;
    const float* Bptr = Bm + (size_t)bkk * Nn + n0 + bnq;

    float4 areg = *(const float4*)Aptr;
    float4 breg = *(const float4*)Bptr;

    unsigned long long acc[8][4];
#pragma unroll
    for (int i = 0; i < 8; i++)
#pragma unroll
        for (int j = 0; j < 4; j++) acc[i][j] = 0ull;

    const int nsteps = K >> 3;
    for (int s = 0; s < nsteps; s++) {
        As[akq + 0][arow] = areg.x;
        As[akq + 1][arow] = areg.y;
        As[akq + 2][arow] = areg.z;
        As[akq + 3][arow] = areg.w;
        *(float4*)&Bs[bkk][bnq] = breg;
        __syncthreads();
        if (s + 1 < nsteps) {
            areg = *(const float4*)(Aptr + (s + 1) * 8);
            breg = *(const float4*)(Bptr + (size_t)(s + 1) * 8 * Nn);
        }
#pragma unroll
        for (int kk = 0; kk < 8; kk++) {
            float4 a0 = *(float4*)&As[kk][ty * 4];
            float4 a1 = *(float4*)&As[kk][ty * 4 + 64];
            ulonglong2 b0 = *(ulonglong2*)&Bs[kk][tx * 4];
            ulonglong2 b1 = *(ulonglong2*)&Bs[kk][tx * 4 + 64];
            unsigned long long bb[4] = {b0.x, b0.y, b1.x, b1.y};
            unsigned long long av[8];
            av[0] = pack2(a0.x, a0.x); av[1] = pack2(a0.y, a0.y);
            av[2] = pack2(a0.z, a0.z); av[3] = pack2(a0.w, a0.w);
            av[4] = pack2(a1.x, a1.x); av[5] = pack2(a1.y, a1.y);
            av[6] = pack2(a1.z, a1.z); av[7] = pack2(a1.w, a1.w);
#pragma unroll
            for (int i = 0; i < 8; i++)
#pragma unroll
                for (int j = 0; j < 4; j++) fma2(acc[i][j], av[i], bb[j]);
        }
        __syncthreads();
    }

#pragma unroll
    for (int i = 0; i < 8; i++) {
        int row = m0 + ty * 4 + (i & 3) + ((i >= 4) ? 64 : 0);
        float mk = C2masked ? (g_mask[row] ? 1.0f : 0.0f) : 0.0f;
#pragma unroll
        for (int half = 0; half < 2; half++) {
            int col = n0 + tx * 4 + half * 64;
            float2 v0 = unpack2(acc[i][half * 2 + 0]);
            float2 v1 = unpack2(acc[i][half * 2 + 1]);
            float4 v = make_float4(v0.x, v0.y, v1.x, v1.y);
            if (bias) {
                v.x += bias[col]; v.y += bias[col + 1];
                v.z += bias[col + 2]; v.w += bias[col + 3];
            }
            if (do_gelu) {
                v.x = gelu_exact(v.x); v.y = gelu_exact(v.y);
                v.z = gelu_exact(v.z); v.w = gelu_exact(v.w);
            }
            *(float4*)&C[(size_t)row * Nn + col] = v;
            if (C2masked) {
                float4 vm = make_float4(v.x * mk, v.y * mk, v.z * mk, v.w * mk);
                *(float4*)&C2masked[(size_t)row * Nn + col] = vm;
            }
        }
    }
}

// ---------------------------------------------------------------------------
// q softmax (+rope, *0.125) and masked v
// ---------------------------------------------------------------------------
__global__ void q_v_kernel() {
    const int row = blockIdx.x;
    const int pos = row & (N - 1);
    const int tid = threadIdx.x;
    const int w = tid >> 5;
    const int l = tid & 31;

    float inv = expf(-(float)(2 * l) * (1.0f / 64.0f) * logf(10000.0f));
    float arg = (float)pos * inv;
    const float* qrow = g_qkv + (size_t)row * (3 * INNER);
    float x1 = qrow[w * 64 + l]      + sinf(arg);
    float x2 = qrow[w * 64 + l + 32] + cosf(arg);
    float m = fmaxf(x1, x2);
#pragma unroll
    for (int o = 16; o > 0; o >>= 1) m = fmaxf(m, __shfl_xor_sync(0xffffffffu, m, o));
    float e1 = expf(x1 - m), e2 = expf(x2 - m);
    float s = e1 + e2;
#pragma unroll
    for (int o = 16; o > 0; o >>= 1) s += __shfl_xor_sync(0xffffffffu, s, o);
    float r = 0.125f / s;
    g_qs[(size_t)row * INNER + w * 64 + l]      = e1 * r;
    g_qs[(size_t)row * INNER + w * 64 + l + 32] = e2 * r;

    float mk = g_mask[row] ? 1.0f : 0.0f;
    for (int i = tid; i < INNER; i += 256)
        g_vm[(size_t)row * INNER + i] = mk * qrow[2 * INNER + i];
}

// ---------------------------------------------------------------------------
// k column softmax over sequence axis
// ---------------------------------------------------------------------------
__global__ void k_colsoftmax_kernel() {
    const int col = blockIdx.x;
    const int b = blockIdx.y;
    const int d = col & 63;
    const int tid = threadIdx.x;
    __shared__ float red[256];

    int i_ = (d < 32) ? d : (d - 32);
    float inv = expf(-(float)(2 * i_) * (1.0f / 64.0f) * logf(10000.0f));
    bool use_sin = (d < 32);

    float vals[8];
    float mx = -FLT_MAX;
#pragma unroll
    for (int j = 0; j < 8; j++) {
        int n = tid + 256 * j;
        int row = b * N + n;
        float arg = (float)n * inv;
        float rope = use_sin ? sinf(arg) : cosf(arg);
        float v = g_qkv[(size_t)row * (3 * INNER) + INNER + col] + rope;
        v = g_mask[row] ? v : -FLT_MAX;
        vals[j] = v;
        mx = fmaxf(mx, v);
    }
    red[tid] = mx; __syncthreads();
    for (int o = 128; o > 0; o >>= 1) {
        if (tid < o) red[tid] = fmaxf(red[tid], red[tid + o]);
        __syncthreads();
    }
    mx = red[0]; __syncthreads();

    float s = 0.f;
    float ev[8];
#pragma unroll
    for (int j = 0; j < 8; j++) {
        ev[j] = (vals[j] == -FLT_MAX) ? 0.f : expf(vals[j] - mx);
        s += ev[j];
    }
    red[tid] = s; __syncthreads();
    for (int o = 128; o > 0; o >>= 1) {
        if (tid < o) red[tid] += red[tid + o];
        __syncthreads();
    }
    float rs = 1.0f / red[0];
#pragma unroll
    for (int j = 0; j < 8; j++) {
        int n = tid + 256 * j;
        g_ks[(size_t)(b * N + n) * INNER + col] = ev[j] * rs;
    }
}

// ---------------------------------------------------------------------------
// context partial + reduce
// ---------------------------------------------------------------------------
__global__ void ctx_partial_kernel() {
    const int bh = blockIdx.x;
    const int split = blockIdx.y;
    const int b = bh >> 3, h = bh & 7;
    const int tid = threadIdx.x;
    const int ty = tid >> 4, tx = tid & 15;
    __shared__ float Ks[16][64];
    __shared__ float Vs[16][64];

    float acc[4][4];
#pragma unroll
    for (int i = 0; i < 4; i++)
#pragma unroll
        for (int j = 0; j < 4; j++) acc[i][j] = 0.f;

    const int n0 = split * 256;
    for (int c = 0; c < 16; c++) {
        int nb = n0 + c * 16;
        int r = tid >> 6, colc = tid & 63;
#pragma unroll
        for (int i = 0; i < 4; i++) {
            int rr = r + 4 * i;
            size_t base = (size_t)(b * N + nb + rr) * INNER + h * 64 + colc;
            Ks[rr][colc] = g_ks[base];
            Vs[rr][colc] = g_vm[base];
        }
        __syncthreads();
#pragma unroll
        for (int kk = 0; kk < 16; kk++) {
            float a[4], bb[4];
#pragma unroll
            for (int i = 0; i < 4; i++) a[i] = Ks[kk][ty * 4 + i];
#pragma unroll
            for (int j = 0; j < 4; j++) bb[j] = Vs[kk][tx * 4 + j];
#pragma unroll
            for (int i = 0; i < 4; i++)
#pragma unroll
                for (int j = 0; j < 4; j++) acc[i][j] = fmaf(a[i], bb[j], acc[i][j]);
        }
        __syncthreads();
    }
    float* dst = g_ctx_part + (size_t)(bh * 8 + split) * 4096;
#pragma unroll
    for (int i = 0; i < 4; i++)
#pragma unroll
        for (int j = 0; j < 4; j++)
            dst[(ty * 4 + i) * 64 + tx * 4 + j] = acc[i][j];
}

__global__ void ctx_reduce_kernel() {
    int i = blockIdx.x * blockDim.x + threadIdx.x;
    if (i >= B * HEADS * 4096) return;
    int bh = i >> 12, pos = i & 4095;
    float s = 0.f;
#pragma unroll
    for (int sp = 0; sp < 8; sp++) s += g_ctx_part[(size_t)(bh * 8 + sp) * 4096 + pos];
    g_ctx[i] = s;
}

// ---------------------------------------------------------------------------
// apply context to q
// ---------------------------------------------------------------------------
__global__ void attn_apply_kernel() {
    const int blk = blockIdx.x;
    const int tile = blk & 63;
    const int h = (blk >> 6) & 7;
    const int b = blk >> 9;
    const int t0 = tile * 32;
    const int tid = threadIdx.x;
    __shared__ float ctx_sh[64 * 65];
    __shared__ float qs_sh[32 * 64];

    const float* ctxp = g_ctx + (size_t)(b * 8 + h) * 4096;
#pragma unroll
    for (int i = 0; i < 16; i++) {
        int idx = tid + 256 * i;
        ctx_sh[(idx >> 6) * 65 + (idx & 63)] = ctxp[idx];
    }
#pragma unroll
    for (int i = 0; i < 8; i++) {
        int idx = tid + 256 * i;
        int tok = idx >> 6, d = idx & 63;
        qs_sh[idx] = g_qs[(size_t)(b * N + t0 + tok) * INNER + h * 64 + d];
    }
    __syncthreads();
#pragma unroll
    for (int o = 0; o < 8; o++) {
        int idx = tid + 256 * o;
        int tok = idx >> 6, e = idx & 63;
        float s = 0.f;
#pragma unroll
        for (int d = 0; d < 64; d++)
            s = fmaf(qs_sh[tok * 64 + d], ctx_sh[d * 65 + e], s);
        g_attn[(size_t)(b * N + t0 + tok) * INNER + h * 64 + e] = s;
    }
}

// ---------------------------------------------------------------------------
// conv weight transpose: w[co][ci][k] -> wk[k][ci][co]
// ---------------------------------------------------------------------------
__global__ void wtrans_kernel(const float* __restrict__ w, float* __restrict__ wk, int Kt) {
    int idx = blockIdx.x * blockDim.x + threadIdx.x;
    int total = DIM * DIM * Kt;
    if (idx >= total) return;
    int co = idx / (DIM * Kt);
    int r = idx - co * (DIM * Kt);
    int ci = r / Kt;
    int k = r - ci * Kt;
    wk[((size_t)k * DIM + ci) * DIM + co] = w[idx];
}

// ---------------------------------------------------------------------------
// implicit-GEMM dilated conv1d, 128x128 tile, f32x2 FMAs
// grid: (co_tiles=4, t_tiles=16, b=4), block 256
// ---------------------------------------------------------------------------
__global__ void conv_gemm128_kernel(const float* __restrict__ wk,
                                    const float* __restrict__ bias,
                                    const float* __restrict__ base,
                                    float* __restrict__ out, int dil) {
    __shared__ float Xs[8][132];
    __shared__ float Ws[8][128];
    const int co0 = blockIdx.x * 128;
    const int t0 = blockIdx.y * 128;
    const int b = blockIdx.z;
    const int tid = threadIdx.x;
    const int tx = tid & 15, ty = tid >> 4;

    const int arow = tid >> 1;
    const int akq  = (tid & 1) * 4;
    const int bkk  = tid >> 5;
    const int bnq  = (tid & 31) * 4;

    unsigned long long acc[8][4];
#pragma unroll
    for (int i = 0; i < 8; i++)
#pragma unroll
        for (int j = 0; j < 4; j++) acc[i][j] = 0ull;

    const int total = 9 * 64;   // taps * (512/8)

    // prologue load (s = 0): tap 0, ci0 = 0
    float4 areg, breg;
    {
        int shift = (0 - 4) * dil;
        int tt = t0 + arow + shift;
        areg = make_float4(0.f, 0.f, 0.f, 0.f);
        if (tt >= 0 && tt < N)
            areg = *(const float4*)&g_xm[(size_t)(b * N + tt) * DIM + akq];
        breg = *(const float4*)&wk[(size_t)bkk * DIM + co0 + bnq];
    }

    for (int s = 0; s < total; s++) {
        Xs[akq + 0][arow] = areg.x;
        Xs[akq + 1][arow] = areg.y;
        Xs[akq + 2][arow] = areg.z;
        Xs[akq + 3][arow] = areg.w;
        *(float4*)&Ws[bkk][bnq] = breg;
        __syncthreads();
        if (s + 1 < total) {
            int s2 = s + 1;
            int k2 = s2 >> 6;
            int ci2 = (s2 & 63) * 8;
            int shift = (k2 - 4) * dil;
            int tt = t0 + arow + shift;
            areg = make_float4(0.f, 0.f, 0.f, 0.f);
            if (tt >= 0 && tt < N)
                areg = *(const float4*)&g_xm[(size_t)(b * N + tt) * DIM + ci2 + akq];
            breg = *(const float4*)&wk[((size_t)k2 * DIM + ci2 + bkk) * DIM + co0 + bnq];
        }
#pragma unroll
        for (int kk = 0; kk < 8; kk++) {
            float4 a0 = *(float4*)&Xs[kk][ty * 4];
            float4 a1 = *(float4*)&Xs[kk][ty * 4 + 64];
            ulonglong2 b0 = *(ulonglong2*)&Ws[kk][tx * 4];
            ulonglong2 b1 = *(ulonglong2*)&Ws[kk][tx * 4 + 64];
            unsigned long long bb[4] = {b0.x, b0.y, b1.x, b1.y};
            unsigned long long av[8];
            av[0] = pack2(a0.x, a0.x); av[1] = pack2(a0.y, a0.y);
            av[2] = pack2(a0.z, a0.z); av[3] = pack2(a0.w, a0.w);
            av[4] = pack2(a1.x, a1.x); av[5] = pack2(a1.y, a1.y);
            av[6] = pack2(a1.z, a1.z); av[7] = pack2(a1.w, a1.w);
#pragma unroll
            for (int i = 0; i < 8; i++)
#pragma unroll
                for (int j = 0; j < 4; j++) fma2(acc[i][j], av[i], bb[j]);
        }
        __syncthreads();
    }

#pragma unroll
    for (int i = 0; i < 8; i++) {
        int t = t0 + ty * 4 + (i & 3) + ((i >= 4) ? 64 : 0);
#pragma unroll
        for (int half = 0; half < 2; half++) {
            int co = co0 + tx * 4 + half * 64;
            size_t idx = (size_t)(b * N + t) * DIM + co;
            float2 v0 = unpack2(acc[i][half * 2 + 0]);
            float2 v1 = unpack2(acc[i][half * 2 + 1]);
            float4 bs = *(const float4*)&base[idx];
            float4 v;
            v.x = bs.x + gelu_exact(v0.x + bias[co]);
            v.y = bs.y + gelu_exact(v0.y + bias[co + 1]);
            v.z = bs.z + gelu_exact(v1.x + bias[co + 2]);
            v.w = bs.w + gelu_exact(v1.y + bias[co + 3]);
            *(float4*)&out[idx] = v;
        }
    }
}

// ---------------------------------------------------------------------------
// layer norm
// ---------------------------------------------------------------------------
__global__ void ln_kernel(const float* __restrict__ x,
                          const float* __restrict__ g,
                          const float* __restrict__ bvec,
                          float* __restrict__ out) {
    const int row = blockIdx.x;
    const int tid = threadIdx.x;
    __shared__ float red[256];
    float v0 = x[(size_t)row * DIM + tid];
    float v1 = x[(size_t)row * DIM + tid + 256];
    red[tid] = v0 + v1; __syncthreads();
    for (int o = 128; o > 0; o >>= 1) {
        if (tid < o) red[tid] += red[tid + o];
        __syncthreads();
    }
    float mean = red[0] * (1.0f / DIM); __syncthreads();
    float d0 = v0 - mean, d1 = v1 - mean;
    red[tid] = d0 * d0 + d1 * d1; __syncthreads();
    for (int o = 128; o > 0; o >>= 1) {
        if (tid < o) red[tid] += red[tid + o];
        __syncthreads();
    }
    float var = red[0] * (1.0f / DIM);
    float rstd = rsqrtf(var + 1e-5f);
    out[(size_t)row * DIM + tid]       = d0 * rstd * g[tid] + bvec[tid];
    out[(size_t)row * DIM + tid + 256] = d1 * rstd * g[tid + 256] + bvec[tid + 256];
}

// ---------------------------------------------------------------------------
// Launch
// ---------------------------------------------------------------------------
extern "C" void kernel_launch(void* const* d_in, const int* in_sizes, int n_in,
                              void* d_out, int out_size) {
    const float* tokens   = (const float*)d_in[0];
    const unsigned char* mask_raw = (const unsigned char*)d_in[1];
    const float* w_qkv    = (const float*)d_in[2];
    const float* w_out    = (const float*)d_in[3];
    const float* b_out    = (const float*)d_in[4];
    const float* w_narrow = (const float*)d_in[5];
    const float* b_narrow = (const float*)d_in[6];
    const float* w_wide   = (const float*)d_in[7];
    const float* b_wide   = (const float*)d_in[8];
    const float* ln1_g    = (const float*)d_in[9];
    const float* ln1_b    = (const float*)d_in[10];
    const float* ff_w     = (const float*)d_in[11];
    const float* ff_b     = (const float*)d_in[12];
    const float* ln2_g    = (const float*)d_in[13];
    const float* ln2_b    = (const float*)d_in[14];
    float* outp = (float*)d_out;

    float *p_qkv, *p_qs, *p_ks, *p_vm, *p_attn, *p_tok, *p_xm;
    float *p_wkn, *p_wkw, *p_c1, *p_c2, *p_ln1, *p_ff;
    cudaGetSymbolAddress((void**)&p_qkv, g_qkv);
    cudaGetSymbolAddress((void**)&p_qs,  g_qs);
    cudaGetSymbolAddress((void**)&p_ks,  g_ks);
    cudaGetSymbolAddress((void**)&p_vm,  g_vm);
    cudaGetSymbolAddress((void**)&p_attn,g_attn);
    cudaGetSymbolAddress((void**)&p_tok, g_tok);
    cudaGetSymbolAddress((void**)&p_xm,  g_xm);
    cudaGetSymbolAddress((void**)&p_wkn, g_wkn);
    cudaGetSymbolAddress((void**)&p_wkw, g_wkw);
    cudaGetSymbolAddress((void**)&p_c1,  g_c1);
    cudaGetSymbolAddress((void**)&p_c2,  g_c2);
    cudaGetSymbolAddress((void**)&p_ln1, g_ln1);
    cudaGetSymbolAddress((void**)&p_ff,  g_ff);

    // 1. mask
    mask_prep_kernel<<<1, 256>>>(mask_raw);

    // 2. qkv GEMM: (8192 x 512) @ (512 x 1536)
    sgemm128_kernel<<<dim3(3 * INNER / 128, ROWS / 128), 256>>>(
        tokens, w_qkv, nullptr, p_qkv, nullptr, ROWS, 3 * INNER, DIM, 0);

    // 3. q softmax + masked v
    q_v_kernel<<<ROWS, 256>>>();

    // 4. k column softmax
    k_colsoftmax_kernel<<<dim3(INNER, B), 256>>>();

    // 5. context
    ctx_partial_kernel<<<dim3(B * HEADS, 8), 256>>>();
    ctx_reduce_kernel<<<(B * HEADS * 4096 + 255) / 256, 256>>>();

    // 6. apply context to q
    attn_apply_kernel<<<B * HEADS * (N / 32), 256>>>();

    // 7. out projection (+bias) with fused masked copy for conv input
    sgemm128_kernel<<<dim3(DIM / 128, ROWS / 128), 256>>>(
        p_attn, w_out, b_out, p_tok, p_xm, ROWS, DIM, INNER, 0);

    // 8. conv weight transposes
    wtrans_kernel<<<(DIM * DIM * NARROW_K + 255) / 256, 256>>>(w_narrow, p_wkn, NARROW_K);
    wtrans_kernel<<<(DIM * DIM * WIDE_K + 255) / 256, 256>>>(w_wide, p_wkw, WIDE_K);

    // 9. convs (implicit GEMM) with fused residual + gelu
    conv_gemm128_kernel<<<dim3(DIM / 128, N / 128, B), 256>>>(p_wkn, b_narrow, p_tok, p_c1, 1);
    conv_gemm128_kernel<<<dim3(DIM / 128, N / 128, B), 256>>>(p_wkw, b_wide, p_c1, p_c2, WIDE_DIL);

    // 10. ln1
    ln_kernel<<<ROWS, 256>>>(p_c2, ln1_g, ln1_b, p_ln1);

    // 11. ff GEMM + bias + gelu
    sgemm128_kernel<<<dim3(DIM / 128, ROWS / 128), 256>>>(
        p_ln1, ff_w, ff_b, p_ff, nullptr, ROWS, DIM, DIM, 1);

    // 12. ln2 -> output
    ln_kernel<<<ROWS, 256>>>(p_ff, ln2_g, ln2_b, outp);
}